// round 2
// baseline (speedup 1.0000x reference)
#include <cuda_runtime.h>
#include <cuda_bf16.h>

#define N_NODES 100000
#define N_EDGES 1600000
#define D_IN    128
#define D_HID   256
#define N_CLS   10

// ---------------- scratch (no allocs allowed) ----------------
__device__ __align__(128) float g_agg[(size_t)N_NODES * D_IN];   // 51.2 MB
__device__ __align__(128) float g_deg[N_NODES];
__device__ __align__(128) float g_pooled[D_HID];
__device__ int g_idx32;   // 1 => edge_index is int32, 0 => int64

// ---------------- probe edge_index dtype ----------------
__global__ void probe_kernel(const long long* __restrict__ ei64) {
    // Interpret first 1024 entries as int64. If the data is really int32,
    // pairs (lo, hi) of random values in [0, 1e5) form huge int64s -> out of range.
    __shared__ int bad;
    if (threadIdx.x == 0) bad = 0;
    __syncthreads();
    long long v = ei64[threadIdx.x];
    if (v < 0 || v >= N_NODES) atomicOr(&bad, 1);
    __syncthreads();
    if (threadIdx.x == 0) g_idx32 = bad ? 1 : 0;
}

// ---------------- zero scratch ----------------
__global__ void zero_kernel() {
    size_t i = (size_t)blockIdx.x * blockDim.x + threadIdx.x;
    size_t stride = (size_t)gridDim.x * blockDim.x;
    float4 z = make_float4(0.f, 0.f, 0.f, 0.f);
    size_t n4 = (size_t)N_NODES * (D_IN / 4);
    for (size_t j = i; j < n4; j += stride) ((float4*)g_agg)[j] = z;
    for (size_t j = i; j < N_NODES; j += stride) g_deg[j] = 0.f;
    if (i < D_HID) g_pooled[i] = 0.f;
}

// ---------------- edge aggregation: one warp per edge ----------------
__global__ __launch_bounds__(256) void edge_kernel(
    const float* __restrict__ x, const void* __restrict__ ei_raw)
{
    const int lane  = threadIdx.x & 31;
    const int gwarp = (blockIdx.x * blockDim.x + threadIdx.x) >> 5;
    const int nwarp = (gridDim.x * blockDim.x) >> 5;
    const int is32  = g_idx32;
    const int*       ei32 = (const int*)ei_raw;
    const long long* ei64 = (const long long*)ei_raw;

    for (int e = gwarp; e < N_EDGES; e += nwarp) {
        long long src, tgt;
        if (is32) {
            src = ei32[e];
            tgt = ei32[N_EDGES + e];
        } else {
            src = ei64[e];
            tgt = ei64[(size_t)N_EDGES + e];
        }
        if ((unsigned long long)src >= N_NODES ||
            (unsigned long long)tgt >= N_NODES) continue;  // defensive
        float4 v = __ldg((const float4*)(x + (size_t)src * D_IN) + lane);
        float* dst = g_agg + (size_t)tgt * D_IN + lane * 4;
        asm volatile("red.global.add.v4.f32 [%0], {%1, %2, %3, %4};"
                     :: "l"(dst), "f"(v.x), "f"(v.y), "f"(v.z), "f"(v.w)
                     : "memory");
        if (lane == 0) atomicAdd(&g_deg[tgt], 1.0f);
    }
}

// ---------------- fused GEMM + bias + ReLU + mean-pool ----------------
// Only layer 2 survives: h = relu(agg @ Wl2^T + x @ Wr2^T + bias2).
// Block: 256 threads, tile = 64 nodes x 128 outputs (blockIdx.y picks j-half).
#define WPAD 132                 // 128 + 4 pad: conflict-free LDS.128
#define TILE_N 64

__global__ __launch_bounds__(256) void gemm_pool_kernel(
    const float* __restrict__ x,  const float* __restrict__ Wl,
    const float* __restrict__ Wr, const float* __restrict__ bias)
{
    extern __shared__ float sm[];
    float* Wls = sm;                       // [128][WPAD]
    float* Wrs = sm + 128 * WPAD;          // [128][WPAD]
    float* ags = sm + 2 * 128 * WPAD;      // [64][WPAD]
    float* xxs = ags + TILE_N * WPAD;      // [64][WPAD]

    const int t    = threadIdx.x;
    const int lane = t & 31;
    const int wrp  = t >> 5;
    const int jhalf = blockIdx.y;

    const float* Wl2 = Wl + 2 * D_HID * D_IN + jhalf * 128 * D_IN;
    const float* Wr2 = Wr + 2 * D_HID * D_IN + jhalf * 128 * D_IN;

    // load weight halves into smem (once per block)
    for (int i = t; i < 128 * 32; i += 256) {
        int r = i >> 5, c4 = i & 31;
        float4 a = __ldg((const float4*)(Wl2 + r * D_IN) + c4);
        float4 b = __ldg((const float4*)(Wr2 + r * D_IN) + c4);
        *(float4*)(Wls + r * WPAD + c4 * 4) = a;
        *(float4*)(Wrs + r * WPAD + c4 * 4) = b;
    }

    float bj[4];
#pragma unroll
    for (int jj = 0; jj < 4; jj++)
        bj[jj] = __ldg(bias + 2 * D_HID + jhalf * 128 + lane + 32 * jj);

    float pool[4] = {0.f, 0.f, 0.f, 0.f};

    const int ntiles = (N_NODES + TILE_N - 1) / TILE_N;
    for (int tile = blockIdx.x; tile < ntiles; tile += gridDim.x) {
        __syncthreads();   // smem reuse barrier (covers first-iter weight load too)
        int base = tile * TILE_N;

        // stage 64-node input tile (agg scaled by 1/deg, and x)
        for (int i = t; i < TILE_N * 32; i += 256) {
            int nl = i >> 5, c4 = i & 31;
            int node = base + nl;
            float4 av = make_float4(0.f, 0.f, 0.f, 0.f);
            float4 xv = av;
            if (node < N_NODES) {
                float inv = 1.0f / fmaxf(g_deg[node], 1.0f);
                av = *((const float4*)(g_agg + (size_t)node * D_IN) + c4);
                xv = __ldg((const float4*)(x + (size_t)node * D_IN) + c4);
                av.x *= inv; av.y *= inv; av.z *= inv; av.w *= inv;
            }
            *(float4*)(ags + nl * WPAD + c4 * 4) = av;
            *(float4*)(xxs + nl * WPAD + c4 * 4) = xv;
        }
        __syncthreads();

        float acc[8][4];
#pragma unroll
        for (int n = 0; n < 8; n++)
#pragma unroll
            for (int jj = 0; jj < 4; jj++) acc[n][jj] = 0.f;

#pragma unroll 1
        for (int m = 0; m < 2; m++) {
            const float* Ws = m ? Wrs : Wls;
            const float* Us = m ? xxs : ags;
#pragma unroll 4
            for (int k4 = 0; k4 < 32; k4++) {
                float4 w[4], u[8];
#pragma unroll
                for (int jj = 0; jj < 4; jj++)
                    w[jj] = *(const float4*)(Ws + (lane + 32 * jj) * WPAD + k4 * 4);
#pragma unroll
                for (int n = 0; n < 8; n++)
                    u[n] = *(const float4*)(Us + (wrp * 8 + n) * WPAD + k4 * 4);
#pragma unroll
                for (int n = 0; n < 8; n++)
#pragma unroll
                    for (int jj = 0; jj < 4; jj++) {
                        acc[n][jj] = fmaf(u[n].x, w[jj].x, acc[n][jj]);
                        acc[n][jj] = fmaf(u[n].y, w[jj].y, acc[n][jj]);
                        acc[n][jj] = fmaf(u[n].z, w[jj].z, acc[n][jj]);
                        acc[n][jj] = fmaf(u[n].w, w[jj].w, acc[n][jj]);
                    }
            }
        }

        // bias + relu + local pool accumulation (mask out-of-range nodes)
#pragma unroll
        for (int n = 0; n < 8; n++) {
            if (base + wrp * 8 + n < N_NODES) {
#pragma unroll
                for (int jj = 0; jj < 4; jj++)
                    pool[jj] += fmaxf(acc[n][jj] + bj[jj], 0.f);
            }
        }
    }

#pragma unroll
    for (int jj = 0; jj < 4; jj++)
        atomicAdd(&g_pooled[jhalf * 128 + lane + 32 * jj], pool[jj]);
}

// ---------------- head: mean, MLP, log_softmax ----------------
__global__ __launch_bounds__(320) void head_kernel(
    const float* __restrict__ W1, const float* __restrict__ b1,
    const float* __restrict__ W2, const float* __restrict__ b2,
    float* __restrict__ out)
{
    __shared__ float pm[D_HID];
    __shared__ float z1[D_HID];
    __shared__ float z2[N_CLS];
    int t = threadIdx.x;

    if (t < D_HID) pm[t] = g_pooled[t] * (1.0f / (float)N_NODES);
    __syncthreads();

    if (t < D_HID) {
        float s = b1[t];
        const float* w = W1 + t * D_HID;
#pragma unroll 8
        for (int j = 0; j < D_HID; j++) s = fmaf(w[j], pm[j], s);
        z1[t] = fmaxf(s, 0.f);
    }
    __syncthreads();

    int wrp = t >> 5, lane = t & 31;
    if (wrp < N_CLS) {
        float s2 = 0.f;
        for (int i = lane; i < D_HID; i += 32) s2 = fmaf(W2[wrp * D_HID + i], z1[i], s2);
#pragma unroll
        for (int o = 16; o; o >>= 1) s2 += __shfl_xor_sync(0xffffffffu, s2, o);
        if (lane == 0) z2[wrp] = s2 + b2[wrp];
    }
    __syncthreads();

    if (t == 0) {
        float m = z2[0];
#pragma unroll
        for (int c = 1; c < N_CLS; c++) m = fmaxf(m, z2[c]);
        float se = 0.f;
#pragma unroll
        for (int c = 0; c < N_CLS; c++) se += expf(z2[c] - m);
        float lse = logf(se);
#pragma unroll
        for (int c = 0; c < N_CLS; c++) out[c] = z2[c] - m - lse;
    }
}

// ---------------- launch ----------------
extern "C" void kernel_launch(void* const* d_in, const int* in_sizes, int n_in,
                              void* d_out, int out_size)
{
    const float* x    = (const float*)d_in[0];
    const void*  ei   = d_in[1];
    const float* Wl   = (const float*)d_in[2];
    const float* Wr   = (const float*)d_in[3];
    const float* bias = (const float*)d_in[4];
    const float* W1   = (const float*)d_in[5];
    const float* b1   = (const float*)d_in[6];
    const float* W2   = (const float*)d_in[7];
    const float* b2   = (const float*)d_in[8];
    float* out = (float*)d_out;

    probe_kernel<<<1, 1024>>>((const long long*)ei);
    zero_kernel<<<1024, 256>>>();
    edge_kernel<<<1184, 256>>>(x, ei);

    size_t smem = (size_t)(2 * 128 * WPAD + 2 * TILE_N * WPAD) * sizeof(float);
    cudaFuncSetAttribute(gemm_pool_kernel,
                         cudaFuncAttributeMaxDynamicSharedMemorySize, (int)smem);
    dim3 grid(74, 2);
    gemm_pool_kernel<<<grid, 256, smem>>>(x, Wl, Wr, bias);

    head_kernel<<<1, 320>>>(W1, b1, W2, b2, out);
}

// round 4
// speedup vs baseline: 2.6296x; 2.6296x over previous
#include <cuda_runtime.h>
#include <cuda_bf16.h>
#include <cstdint>

#define N_NODES 100000
#define N_EDGES 1600000
#define D_IN    128
#define D_HID   256
#define N_CLS   10
#define NTILES  782                  // ceil(100000/128)
#define PAD_NODES (NTILES * 128)     // 100096
#define PAD_ROWS  (PAD_NODES - N_NODES)   // 96

// ---------------- scratch (no allocs allowed) ----------------
__device__ __align__(128) float g_agg[(size_t)N_NODES * D_IN];          // 51.2 MB
__device__ __align__(128) float g_deg[N_NODES];
__device__ __align__(128) float g_pooled[D_HID];
__device__ __align__(128) uint32_t g_Afrag[(size_t)PAD_NODES * 128];    // 51.2 MB, A in mma-frag order
__device__ __align__(128) uint32_t g_Bfrag[65536];                      // 256 KB, W hi/lo in frag order
__device__ int g_idx32;

// ---------------- probe edge_index dtype ----------------
__global__ void probe_kernel(const long long* __restrict__ ei64) {
    __shared__ int bad;
    if (threadIdx.x == 0) bad = 0;
    __syncthreads();
    long long v = ei64[threadIdx.x];
    if (v < 0 || v >= N_NODES) atomicOr(&bad, 1);
    __syncthreads();
    if (threadIdx.x == 0) g_idx32 = bad ? 1 : 0;
}

// ---------------- zero scratch ----------------
__global__ void zero_kernel() {
    size_t i = (size_t)blockIdx.x * blockDim.x + threadIdx.x;
    size_t stride = (size_t)gridDim.x * blockDim.x;
    float4 z = make_float4(0.f, 0.f, 0.f, 0.f);
    size_t n4 = (size_t)N_NODES * (D_IN / 4);
    for (size_t j = i; j < n4; j += stride) ((float4*)g_agg)[j] = z;
    for (size_t j = i; j < N_NODES; j += stride) g_deg[j] = 0.f;
    if (i < D_HID) g_pooled[i] = 0.f;
}

// ---------------- edge aggregation: one warp per edge ----------------
__global__ __launch_bounds__(256) void edge_kernel(
    const float* __restrict__ x, const void* __restrict__ ei_raw)
{
    const int lane  = threadIdx.x & 31;
    const int gwarp = (blockIdx.x * blockDim.x + threadIdx.x) >> 5;
    const int nwarp = (gridDim.x * blockDim.x) >> 5;
    const int is32  = g_idx32;
    const int*       ei32 = (const int*)ei_raw;
    const long long* ei64 = (const long long*)ei_raw;

    for (int e = gwarp; e < N_EDGES; e += nwarp) {
        long long src, tgt;
        if (is32) { src = ei32[e]; tgt = ei32[N_EDGES + e]; }
        else      { src = ei64[e]; tgt = ei64[(size_t)N_EDGES + e]; }
        if ((unsigned long long)src >= N_NODES ||
            (unsigned long long)tgt >= N_NODES) continue;
        float4 v = __ldg((const float4*)(x + (size_t)src * D_IN) + lane);
        float* dst = g_agg + (size_t)tgt * D_IN + lane * 4;
        asm volatile("red.global.add.v4.f32 [%0], {%1, %2, %3, %4};"
                     :: "l"(dst), "f"(v.x), "f"(v.y), "f"(v.z), "f"(v.w) : "memory");
        if (lane == 0) atomicAdd(&g_deg[tgt], 1.0f);
    }
}

// ---------------- build A fragments: A = [agg/deg | x] in mma m16k16 order ----------------
// flat u32 index j = (((t*16 + ks)*8 + mtile)*128) + lane*4 + reg
//   row n = t*128 + mtile*16 + (reg&1)*8 + (lane>>2)
//   col k = ks*16 + (reg>>1)*8 + (lane&3)*2       (value packs k, k+1)
__global__ __launch_bounds__(256) void convert_kernel(const float* __restrict__ x) {
    const size_t TOT = (size_t)PAD_NODES * 128;
    size_t j0 = (size_t)blockIdx.x * blockDim.x + threadIdx.x;
    size_t stride = (size_t)gridDim.x * blockDim.x;
    for (size_t j = j0; j < TOT; j += stride) {
        int r  = (int)(j & 3);
        int l  = (int)((j >> 2) & 31);
        int mt = (int)((j >> 7) & 7);
        int ks = (int)((j >> 10) & 15);
        int t  = (int)(j >> 14);
        int n  = t * 128 + mt * 16 + (r & 1) * 8 + (l >> 2);
        int k  = ks * 16 + (r >> 1) * 8 + (l & 3) * 2;
        float f0 = 0.f, f1 = 0.f;
        if (n < N_NODES) {
            if (k < 128) {
                float inv = 1.0f / fmaxf(g_deg[n], 1.0f);
                float2 v = *(const float2*)(g_agg + (size_t)n * D_IN + k);
                f0 = v.x * inv; f1 = v.y * inv;
            } else {
                float2 v = __ldg((const float2*)(x + (size_t)n * D_IN + (k - 128)));
                f0 = v.x; f1 = v.y;
            }
        }
        __nv_bfloat162 p = __floats2bfloat162_rn(f0, f1);
        g_Afrag[j] = *(const uint32_t*)&p;
    }
}

// ---------------- build B fragments: combined W = [Wl2 | Wr2], hi/lo split ----------------
// flat u32 index i = ((((jh*2 + p)*16 + ks)*16 + nt)*32 + l)*2 + r
//   n = jh*128 + nt*8 + (l>>2);  k = ks*16 + r*8 + (l&3)*2   (packs k, k+1)
__global__ void prepw_kernel(const float* __restrict__ Wl, const float* __restrict__ Wr) {
    int i = blockIdx.x * blockDim.x + threadIdx.x;   // 65536 threads
    int r  = i & 1;
    int l  = (i >> 1) & 31;
    int nt = (i >> 6) & 15;
    int ks = (i >> 10) & 15;
    int p  = (i >> 14) & 1;
    int jh = (i >> 15) & 1;
    int n  = jh * 128 + nt * 8 + (l >> 2);
    int k  = ks * 16 + r * 8 + (l & 3) * 2;

    float w0 = (k < 128)     ? Wl[2 * D_HID * D_IN + n * D_IN + k]
                             : Wr[2 * D_HID * D_IN + n * D_IN + (k - 128)];
    float w1 = (k + 1 < 128) ? Wl[2 * D_HID * D_IN + n * D_IN + k + 1]
                             : Wr[2 * D_HID * D_IN + n * D_IN + (k + 1 - 128)];
    __nv_bfloat16 h0 = __float2bfloat16(w0);
    __nv_bfloat16 h1 = __float2bfloat16(w1);
    float v0, v1;
    if (p == 0) { v0 = __bfloat162float(h0); v1 = __bfloat162float(h1); }
    else        { v0 = w0 - __bfloat162float(h0); v1 = w1 - __bfloat162float(h1); }
    __nv_bfloat162 pk = __floats2bfloat162_rn(v0, v1);
    g_Bfrag[i] = *(const uint32_t*)&pk;
}

// ---------------- mma.sync GEMM + bias + relu + pool ----------------
#define MMA16816(d, a, b) \
    asm volatile("mma.sync.aligned.m16n8k16.row.col.f32.bf16.bf16.f32 " \
        "{%0,%1,%2,%3}, {%4,%5,%6,%7}, {%8,%9}, {%0,%1,%2,%3};" \
        : "+f"((d)[0]), "+f"((d)[1]), "+f"((d)[2]), "+f"((d)[3]) \
        : "r"((a)[0]), "r"((a)[1]), "r"((a)[2]), "r"((a)[3]), \
          "r"((b)[0]), "r"((b)[1]))

// 148 CTAs: jhalf = bid&1, cbase = bid>>1 (74 per jhalf). 8 warps.
// Warp grid 2M x 4N; warp tile 64 rows x 32 cols. CTA tile 128 x 128.
__global__ __launch_bounds__(256) void gemm_mma_kernel(const float* __restrict__ bias) {
    extern __shared__ uint32_t sB[];     // 32768 u32 = 128 KB (one jhalf, hi+lo)
    const int tid = threadIdx.x;
    const int lane = tid & 31, wid = tid >> 5;
    const int wm = wid >> 2, wn = wid & 3;
    const int jhalf = blockIdx.x & 1;
    const int cbase = blockIdx.x >> 1;

    // stage B fragments for this jhalf
    {
        const uint4* src = (const uint4*)(g_Bfrag + jhalf * 32768);
        uint4* dst = (uint4*)sB;
        for (int i = tid; i < 32768 / 4; i += 256) dst[i] = __ldg(src + i);
    }
    __syncthreads();

    // bias registers: col = jhalf*128 + wn*32 + ntl*8 + (lane&3)*2 + c
    float br[4][2];
#pragma unroll
    for (int ntl = 0; ntl < 4; ntl++) {
        int col = jhalf * 128 + wn * 32 + ntl * 8 + (lane & 3) * 2;
        br[ntl][0] = __ldg(bias + 2 * D_HID + col);
        br[ntl][1] = __ldg(bias + 2 * D_HID + col + 1);
    }

    float pool[4][2] = {};

    for (int t = cbase; t < NTILES; t += 74) {
        float acc[4][4][4];
#pragma unroll
        for (int ml = 0; ml < 4; ml++)
#pragma unroll
            for (int ntl = 0; ntl < 4; ntl++)
#pragma unroll
                for (int q = 0; q < 4; q++) acc[ml][ntl][q] = 0.f;

        const uint32_t* abase = g_Afrag + (size_t)t * (16 * 8 * 128);
#pragma unroll 2
        for (int ks = 0; ks < 16; ks++) {
            uint32_t a[4][4];
#pragma unroll
            for (int ml = 0; ml < 4; ml++) {
                uint4 v = __ldg((const uint4*)(abase + ((ks * 8) + (wm * 4 + ml)) * 128 + lane * 4));
                a[ml][0] = v.x; a[ml][1] = v.y; a[ml][2] = v.z; a[ml][3] = v.w;
            }
#pragma unroll
            for (int p = 0; p < 2; p++) {
#pragma unroll
                for (int ntl = 0; ntl < 4; ntl++) {
                    uint2 bv = *(const uint2*)(sB + (((p * 16 + ks) * 16 + wn * 4 + ntl) * 32 + lane) * 2);
                    uint32_t b[2] = { bv.x, bv.y };
#pragma unroll
                    for (int ml = 0; ml < 4; ml++) MMA16816(acc[ml][ntl], a[ml], b);
                }
            }
        }

        // bias + relu + pool (over rows)
#pragma unroll
        for (int ml = 0; ml < 4; ml++)
#pragma unroll
            for (int ntl = 0; ntl < 4; ntl++) {
                pool[ntl][0] += fmaxf(acc[ml][ntl][0] + br[ntl][0], 0.f)
                              + fmaxf(acc[ml][ntl][2] + br[ntl][0], 0.f);
                pool[ntl][1] += fmaxf(acc[ml][ntl][1] + br[ntl][1], 0.f)
                              + fmaxf(acc[ml][ntl][3] + br[ntl][1], 0.f);
            }
    }

    // reduce pool over the 8 lanes sharing a column (same lane&3), then atomic
#pragma unroll
    for (int ntl = 0; ntl < 4; ntl++)
#pragma unroll
        for (int c = 0; c < 2; c++) {
            float v = pool[ntl][c];
            v += __shfl_xor_sync(0xffffffffu, v, 16);
            v += __shfl_xor_sync(0xffffffffu, v, 8);
            v += __shfl_xor_sync(0xffffffffu, v, 4);
            if ((lane >> 2) == 0) {
                int col = jhalf * 128 + wn * 32 + ntl * 8 + (lane & 3) * 2 + c;
                atomicAdd(&g_pooled[col], v);
            }
        }
}

// ---------------- head: pad-correction, mean, MLP, log_softmax ----------------
__global__ __launch_bounds__(320) void head_kernel(
    const float* __restrict__ bias,
    const float* __restrict__ W1, const float* __restrict__ b1,
    const float* __restrict__ W2, const float* __restrict__ b2,
    float* __restrict__ out)
{
    __shared__ float pm[D_HID];
    __shared__ float z1[D_HID];
    __shared__ float z2[N_CLS];
    int t = threadIdx.x;

    if (t < D_HID) {
        // padded rows contribute exactly relu(bias) each; remove them
        float pad = (float)PAD_ROWS * fmaxf(bias[2 * D_HID + t], 0.f);
        pm[t] = (g_pooled[t] - pad) * (1.0f / (float)N_NODES);
    }
    __syncthreads();

    if (t < D_HID) {
        float s = b1[t];
        const float* w = W1 + t * D_HID;
#pragma unroll 8
        for (int j = 0; j < D_HID; j++) s = fmaf(w[j], pm[j], s);
        z1[t] = fmaxf(s, 0.f);
    }
    __syncthreads();

    int wrp = t >> 5, lane = t & 31;
    if (wrp < N_CLS) {
        float s2 = 0.f;
        for (int i = lane; i < D_HID; i += 32) s2 = fmaf(W2[wrp * D_HID + i], z1[i], s2);
#pragma unroll
        for (int o = 16; o; o >>= 1) s2 += __shfl_xor_sync(0xffffffffu, s2, o);
        if (lane == 0) z2[wrp] = s2 + b2[wrp];
    }
    __syncthreads();

    if (t == 0) {
        float m = z2[0];
#pragma unroll
        for (int c = 1; c < N_CLS; c++) m = fmaxf(m, z2[c]);
        float se = 0.f;
#pragma unroll
        for (int c = 0; c < N_CLS; c++) se += expf(z2[c] - m);
        float lse = logf(se);
#pragma unroll
        for (int c = 0; c < N_CLS; c++) out[c] = z2[c] - m - lse;
    }
}

// ---------------- launch ----------------
extern "C" void kernel_launch(void* const* d_in, const int* in_sizes, int n_in,
                              void* d_out, int out_size)
{
    const float* x    = (const float*)d_in[0];
    const void*  ei   = d_in[1];
    const float* Wl   = (const float*)d_in[2];
    const float* Wr   = (const float*)d_in[3];
    const float* bias = (const float*)d_in[4];
    const float* W1   = (const float*)d_in[5];
    const float* b1   = (const float*)d_in[6];
    const float* W2   = (const float*)d_in[7];
    const float* b2   = (const float*)d_in[8];
    float* out = (float*)d_out;

    probe_kernel<<<1, 1024>>>((const long long*)ei);
    zero_kernel<<<1024, 256>>>();
    edge_kernel<<<1184, 256>>>(x, ei);
    convert_kernel<<<2048, 256>>>(x);
    prepw_kernel<<<256, 256>>>(Wl, Wr);

    cudaFuncSetAttribute(gemm_mma_kernel,
                         cudaFuncAttributeMaxDynamicSharedMemorySize, 131072);
    gemm_mma_kernel<<<148, 256, 131072>>>(bias);

    head_kernel<<<1, 320>>>(bias, W1, b1, W2, b2, out);
}

// round 5
// speedup vs baseline: 3.5833x; 1.3626x over previous
#include <cuda_runtime.h>
#include <cuda_bf16.h>
#include <cstdint>

#define N_NODES 100000
#define N_EDGES 1600000
#define D_IN    128
#define D_HID   256
#define N_CLS   10
#define NTILES  782                  // ceil(100000/128)
#define PAD_NODES (NTILES * 128)     // 100096
#define PAD_ROWS  (PAD_NODES - N_NODES)   // 96

// ---------------- scratch (no allocs allowed) ----------------
__device__ __align__(128) __nv_bfloat16 g_aggbf[(size_t)N_NODES * 128];  // 25.6 MB
__device__ __align__(128) __nv_bfloat16 g_xbf[(size_t)N_NODES * 128];    // 25.6 MB
__device__ __align__(128) float g_deg[N_NODES];
__device__ __align__(128) float g_pooled[D_HID];
__device__ __align__(128) uint32_t g_Afrag[(size_t)PAD_NODES * 128];     // 51.2 MB
__device__ __align__(128) uint32_t g_Bfrag[65536];                       // 256 KB
__device__ int g_idx32;

// frag index for (n, ks, reg, lane): j = (((t*16+ks)*8+mt)*128) + lane*4 + reg
//   n = t*128 + mt*16 + (reg&1)*8 + (lane>>2);  k = ks*16 + (reg>>1)*8 + (lane&3)*2
__device__ __forceinline__ uint32_t frag_idx(int n, int c8, int q) {
    // c8 = k>>3 (0..31), q = pair within 8 (0..3), k = c8*8 + q*2
    int t = n >> 7, mt = (n >> 4) & 7;
    return (uint32_t)((((t * 16 + (c8 >> 1)) * 8 + mt) * 128)
         + ((n & 7) * 4 + q) * 4 + (c8 & 1) * 2 + ((n >> 3) & 1));
}

// ---------------- probe edge_index dtype ----------------
__global__ void probe_kernel(const long long* __restrict__ ei64) {
    __shared__ int bad;
    if (threadIdx.x == 0) bad = 0;
    __syncthreads();
    long long v = ei64[threadIdx.x];
    if (v < 0 || v >= N_NODES) atomicOr(&bad, 1);
    __syncthreads();
    if (threadIdx.x == 0) g_idx32 = bad ? 1 : 0;
}

// ---------------- zero agg + build x bf16 image + x-half A-frags ----------------
__global__ __launch_bounds__(256) void zero_kernel(const float* __restrict__ x) {
    size_t i0 = (size_t)blockIdx.x * blockDim.x + threadIdx.x;
    size_t stride = (size_t)gridDim.x * blockDim.x;

    uint4 z4 = make_uint4(0, 0, 0, 0);
    const size_t NAGG4 = (size_t)N_NODES * 128 / 8;     // uint4 units
    for (size_t j = i0; j < NAGG4; j += stride) ((uint4*)g_aggbf)[j] = z4;
    for (size_t j = i0; j < N_NODES; j += stride) g_deg[j] = 0.f;
    if (i0 < D_HID) g_pooled[i0] = 0.f;

    // x part: tasks = PAD_NODES * 16 (node, 8-col group)
    const size_t NX = (size_t)PAD_NODES * 16;
    for (size_t j = i0; j < NX; j += stride) {
        int c8x = (int)(j & 15);         // 0..15 -> k in [c8x*8, +8) of x
        int n   = (int)(j >> 4);
        int c8  = c8x + 16;              // frag column group (x half: ks 8..15)
        uint32_t p[4] = {0, 0, 0, 0};
        if (n < N_NODES) {
            float4 a = __ldg((const float4*)(x + (size_t)n * D_IN + c8x * 8));
            float4 b = __ldg((const float4*)(x + (size_t)n * D_IN + c8x * 8 + 4));
            __nv_bfloat162 p0 = __floats2bfloat162_rn(a.x, a.y);
            __nv_bfloat162 p1 = __floats2bfloat162_rn(a.z, a.w);
            __nv_bfloat162 p2 = __floats2bfloat162_rn(b.x, b.y);
            __nv_bfloat162 p3 = __floats2bfloat162_rn(b.z, b.w);
            p[0] = *(uint32_t*)&p0; p[1] = *(uint32_t*)&p1;
            p[2] = *(uint32_t*)&p2; p[3] = *(uint32_t*)&p3;
            ((uint4*)g_xbf)[(size_t)n * 16 + c8x] = make_uint4(p[0], p[1], p[2], p[3]);
        }
#pragma unroll
        for (int q = 0; q < 4; q++) g_Afrag[frag_idx(n, c8, q)] = p[q];
    }
}

// ---------------- edge aggregation: half-warp per edge, bf16 v4 RED ----------------
__global__ __launch_bounds__(256) void edge_kernel(const void* __restrict__ ei_raw) {
    const int l16 = threadIdx.x & 15;
    const int ghw = (blockIdx.x * blockDim.x + threadIdx.x) >> 4;
    const int nhw = (gridDim.x * blockDim.x) >> 4;
    const int is32 = g_idx32;
    const int*       ei32 = (const int*)ei_raw;
    const long long* ei64 = (const long long*)ei_raw;

    for (int e = ghw; e < N_EDGES; e += nhw) {
        long long src, tgt;
        if (is32) { src = ei32[e]; tgt = ei32[N_EDGES + e]; }
        else      { src = ei64[e]; tgt = ei64[(size_t)N_EDGES + e]; }
        if ((unsigned long long)src >= N_NODES ||
            (unsigned long long)tgt >= N_NODES) continue;
        uint4 v = __ldg((const uint4*)(g_xbf + (size_t)src * 128) + l16);
        __nv_bfloat16* dst = g_aggbf + (size_t)tgt * 128 + l16 * 8;
        asm volatile("red.global.add.noftz.v4.bf16x2 [%0], {%1, %2, %3, %4};"
                     :: "l"(dst), "r"(v.x), "r"(v.y), "r"(v.z), "r"(v.w) : "memory");
        if (l16 == 0) atomicAdd(&g_deg[tgt], 1.0f);
    }
}

// ---------------- scale agg by 1/deg and write agg-half A-frags ----------------
__global__ __launch_bounds__(256) void convert_kernel() {
    size_t i0 = (size_t)blockIdx.x * blockDim.x + threadIdx.x;
    size_t stride = (size_t)gridDim.x * blockDim.x;
    const size_t NT = (size_t)PAD_NODES * 16;
    for (size_t j = i0; j < NT; j += stride) {
        int c8 = (int)(j & 15);          // agg half: ks 0..7
        int n  = (int)(j >> 4);
        uint32_t p[4] = {0, 0, 0, 0};
        if (n < N_NODES) {
            uint4 raw = ((const uint4*)g_aggbf)[(size_t)n * 16 + c8];
            float inv = 1.0f / fmaxf(g_deg[n], 1.0f);
            uint32_t rw[4] = { raw.x, raw.y, raw.z, raw.w };
#pragma unroll
            for (int q = 0; q < 4; q++) {
                __nv_bfloat162 bv = *(__nv_bfloat162*)&rw[q];
                float2 f = __bfloat1622float2(bv);
                __nv_bfloat162 o = __floats2bfloat162_rn(f.x * inv, f.y * inv);
                p[q] = *(uint32_t*)&o;
            }
        }
#pragma unroll
        for (int q = 0; q < 4; q++) g_Afrag[frag_idx(n, c8, q)] = p[q];
    }
}

// ---------------- build B fragments: combined W = [Wl2 | Wr2], hi/lo split ----------------
__global__ void prepw_kernel(const float* __restrict__ Wl, const float* __restrict__ Wr) {
    int i = blockIdx.x * blockDim.x + threadIdx.x;   // 65536 threads
    int r  = i & 1;
    int l  = (i >> 1) & 31;
    int nt = (i >> 6) & 15;
    int ks = (i >> 10) & 15;
    int p  = (i >> 14) & 1;
    int jh = (i >> 15) & 1;
    int n  = jh * 128 + nt * 8 + (l >> 2);
    int k  = ks * 16 + r * 8 + (l & 3) * 2;

    float w0 = (k < 128)     ? Wl[2 * D_HID * D_IN + n * D_IN + k]
                             : Wr[2 * D_HID * D_IN + n * D_IN + (k - 128)];
    float w1 = (k + 1 < 128) ? Wl[2 * D_HID * D_IN + n * D_IN + k + 1]
                             : Wr[2 * D_HID * D_IN + n * D_IN + (k + 1 - 128)];
    __nv_bfloat16 h0 = __float2bfloat16(w0);
    __nv_bfloat16 h1 = __float2bfloat16(w1);
    float v0, v1;
    if (p == 0) { v0 = __bfloat162float(h0); v1 = __bfloat162float(h1); }
    else        { v0 = w0 - __bfloat162float(h0); v1 = w1 - __bfloat162float(h1); }
    __nv_bfloat162 pk = __floats2bfloat162_rn(v0, v1);
    g_Bfrag[i] = *(const uint32_t*)&pk;
}

// ---------------- mma.sync GEMM + bias + relu + pool ----------------
#define MMA16816(d, a, b) \
    asm volatile("mma.sync.aligned.m16n8k16.row.col.f32.bf16.bf16.f32 " \
        "{%0,%1,%2,%3}, {%4,%5,%6,%7}, {%8,%9}, {%0,%1,%2,%3};" \
        : "+f"((d)[0]), "+f"((d)[1]), "+f"((d)[2]), "+f"((d)[3]) \
        : "r"((a)[0]), "r"((a)[1]), "r"((a)[2]), "r"((a)[3]), \
          "r"((b)[0]), "r"((b)[1]))

__global__ __launch_bounds__(256) void gemm_mma_kernel(const float* __restrict__ bias) {
    extern __shared__ uint32_t sB[];     // 32768 u32 = 128 KB (one jhalf, hi+lo)
    const int tid = threadIdx.x;
    const int lane = tid & 31, wid = tid >> 5;
    const int wm = wid >> 2, wn = wid & 3;
    const int jhalf = blockIdx.x & 1;
    const int cbase = blockIdx.x >> 1;

    {
        const uint4* src = (const uint4*)(g_Bfrag + jhalf * 32768);
        uint4* dst = (uint4*)sB;
        for (int i = tid; i < 32768 / 4; i += 256) dst[i] = __ldg(src + i);
    }
    __syncthreads();

    float br[4][2];
#pragma unroll
    for (int ntl = 0; ntl < 4; ntl++) {
        int col = jhalf * 128 + wn * 32 + ntl * 8 + (lane & 3) * 2;
        br[ntl][0] = __ldg(bias + 2 * D_HID + col);
        br[ntl][1] = __ldg(bias + 2 * D_HID + col + 1);
    }

    float pool[4][2] = {};

    for (int t = cbase; t < NTILES; t += 74) {
        float acc[4][4][4];
#pragma unroll
        for (int ml = 0; ml < 4; ml++)
#pragma unroll
            for (int ntl = 0; ntl < 4; ntl++)
#pragma unroll
                for (int q = 0; q < 4; q++) acc[ml][ntl][q] = 0.f;

        const uint32_t* abase = g_Afrag + (size_t)t * (16 * 8 * 128);
#pragma unroll 2
        for (int ks = 0; ks < 16; ks++) {
            uint32_t a[4][4];
#pragma unroll
            for (int ml = 0; ml < 4; ml++) {
                uint4 v = __ldg((const uint4*)(abase + ((ks * 8) + (wm * 4 + ml)) * 128 + lane * 4));
                a[ml][0] = v.x; a[ml][1] = v.y; a[ml][2] = v.z; a[ml][3] = v.w;
            }
#pragma unroll
            for (int p = 0; p < 2; p++) {
#pragma unroll
                for (int ntl = 0; ntl < 4; ntl++) {
                    uint2 bv = *(const uint2*)(sB + (((p * 16 + ks) * 16 + wn * 4 + ntl) * 32 + lane) * 2);
                    uint32_t b[2] = { bv.x, bv.y };
#pragma unroll
                    for (int ml = 0; ml < 4; ml++) MMA16816(acc[ml][ntl], a[ml], b);
                }
            }
        }

#pragma unroll
        for (int ml = 0; ml < 4; ml++)
#pragma unroll
            for (int ntl = 0; ntl < 4; ntl++) {
                pool[ntl][0] += fmaxf(acc[ml][ntl][0] + br[ntl][0], 0.f)
                              + fmaxf(acc[ml][ntl][2] + br[ntl][0], 0.f);
                pool[ntl][1] += fmaxf(acc[ml][ntl][1] + br[ntl][1], 0.f)
                              + fmaxf(acc[ml][ntl][3] + br[ntl][1], 0.f);
            }
    }

#pragma unroll
    for (int ntl = 0; ntl < 4; ntl++)
#pragma unroll
        for (int c = 0; c < 2; c++) {
            float v = pool[ntl][c];
            v += __shfl_xor_sync(0xffffffffu, v, 16);
            v += __shfl_xor_sync(0xffffffffu, v, 8);
            v += __shfl_xor_sync(0xffffffffu, v, 4);
            if ((lane >> 2) == 0) {
                int col = jhalf * 128 + wn * 32 + ntl * 8 + (lane & 3) * 2 + c;
                atomicAdd(&g_pooled[col], v);
            }
        }
}

// ---------------- head: pad-correction, mean, MLP, log_softmax ----------------
__global__ __launch_bounds__(320) void head_kernel(
    const float* __restrict__ bias,
    const float* __restrict__ W1, const float* __restrict__ b1,
    const float* __restrict__ W2, const float* __restrict__ b2,
    float* __restrict__ out)
{
    __shared__ float pm[D_HID];
    __shared__ float z1[D_HID];
    __shared__ float z2[N_CLS];
    int t = threadIdx.x;

    if (t < D_HID) {
        float pad = (float)PAD_ROWS * fmaxf(bias[2 * D_HID + t], 0.f);
        pm[t] = (g_pooled[t] - pad) * (1.0f / (float)N_NODES);
    }
    __syncthreads();

    if (t < D_HID) {
        float s = b1[t];
        const float* w = W1 + t * D_HID;
#pragma unroll 8
        for (int j = 0; j < D_HID; j++) s = fmaf(w[j], pm[j], s);
        z1[t] = fmaxf(s, 0.f);
    }
    __syncthreads();

    int wrp = t >> 5, lane = t & 31;
    if (wrp < N_CLS) {
        float s2 = 0.f;
        for (int i = lane; i < D_HID; i += 32) s2 = fmaf(W2[wrp * D_HID + i], z1[i], s2);
#pragma unroll
        for (int o = 16; o; o >>= 1) s2 += __shfl_xor_sync(0xffffffffu, s2, o);
        if (lane == 0) z2[wrp] = s2 + b2[wrp];
    }
    __syncthreads();

    if (t == 0) {
        float m = z2[0];
#pragma unroll
        for (int c = 1; c < N_CLS; c++) m = fmaxf(m, z2[c]);
        float se = 0.f;
#pragma unroll
        for (int c = 0; c < N_CLS; c++) se += expf(z2[c] - m);
        float lse = logf(se);
#pragma unroll
        for (int c = 0; c < N_CLS; c++) out[c] = z2[c] - m - lse;
    }
}

// ---------------- launch ----------------
extern "C" void kernel_launch(void* const* d_in, const int* in_sizes, int n_in,
                              void* d_out, int out_size)
{
    const float* x    = (const float*)d_in[0];
    const void*  ei   = d_in[1];
    const float* Wl   = (const float*)d_in[2];
    const float* Wr   = (const float*)d_in[3];
    const float* bias = (const float*)d_in[4];
    const float* W1   = (const float*)d_in[5];
    const float* b1   = (const float*)d_in[6];
    const float* W2   = (const float*)d_in[7];
    const float* b2   = (const float*)d_in[8];
    float* out = (float*)d_out;

    probe_kernel<<<1, 1024>>>((const long long*)ei);
    zero_kernel<<<1184, 256>>>(x);
    edge_kernel<<<1184, 256>>>(ei);
    convert_kernel<<<1184, 256>>>();
    prepw_kernel<<<256, 256>>>(Wl, Wr);

    cudaFuncSetAttribute(gemm_mma_kernel,
                         cudaFuncAttributeMaxDynamicSharedMemorySize, 131072);
    gemm_mma_kernel<<<148, 256, 131072>>>(bias);

    head_kernel<<<1, 320>>>(bias, W1, b1, W2, b2, out);
}